// round 12
// baseline (speedup 1.0000x reference)
#include <cuda_runtime.h>

#define K 32
#define NBUCKET 33
#define ROWS 34           // 33 real buckets + 1 scratch row for dedup'd slots
#define DEAD 33
#define NELEM (32*64*1024)
#define THREADS 128
#define GRID 592          // 148 SMs x 4 CTAs = exactly one wave
#define FULL 0xffffffffu

__device__ float g_A[NBUCKET];
__device__ float g_B[NBUCKET];
__device__ float g_Q;
__device__ unsigned int g_count;

__device__ __forceinline__ float ex2f_(float x) {
    float r; asm("ex2.approx.ftz.f32 %0, %1;" : "=f"(r) : "f"(x)); return r;
}
__device__ __forceinline__ float rsqf_(float x) {
    float r; asm("rsqrt.approx.ftz.f32 %0, %1;" : "=f"(r) : "f"(x)); return r;
}

// Process one float4: bit_code out, (a2,b2) into rank-bucket slab, qacc.
__device__ __forceinline__ float4 do4(float4 xv,
                                      float2* __restrict__ slab,
                                      const float4* __restrict__ tP,
                                      const float4* __restrict__ tQ,
                                      const float* __restrict__ rb,
                                      int tid, float epsB, float& qacc)
{
    const float C5 = 7.21347520444482f;   // 5*log2(e)
    const float SCALE = 0x1p-64f;
    float xs[4] = {xv.x, xv.y, xv.z, xv.w};
    float os[4], as[4], bs[4]; int mm[4];

    #pragma unroll
    for (int c = 0; c < 4; c++) {
        const float xe = xs[c];
        const float A  = ex2f_(-C5 * xe);   // exp(-5x)
        const float B  = ex2f_( C5 * xe);   // exp(+5x)
        const float A2 = A * A;
        const float B2 = B * B;

        int m = 0;                          // rank: 32 independent compares
        #pragma unroll
        for (int k = 0; k < K; k++) m += (xe >= rb[k]) ? 1 : 0;

        const float4 tp = tP[m];
        const float4 tq = tQ[m];
        const float S  = fmaf(A2, tp.x, B2 * tq.x);
        const float Hs = fmaf(A,  tp.y, B  * tq.y);
        const float bR = fmaf(A2, tp.z, B2 * tq.z);
        const float rs = rsqf_(S);
        const float invS = rs * rs;
        qacc  = fmaf(Hs, rs, qacc);
        os[c] = fmaf(bR, invS, epsB);
        as[c] = (A2 * invS) * SCALE;
        bs[c] = (B2 * invS) * SCALE;
        mm[c] = m;
    }

    // Dedup ranks (predicated, branch-free): later absorbs earlier, earlier -> DEAD.
    {
        bool d10 = (mm[1] == mm[0]);
        as[1] += d10 ? as[0] : 0.f;  bs[1] += d10 ? bs[0] : 0.f;
        mm[0]  = d10 ? DEAD : mm[0];
        bool d21 = (mm[2] == mm[1]);
        as[2] += d21 ? as[1] : 0.f;  bs[2] += d21 ? bs[1] : 0.f;
        mm[1]  = d21 ? DEAD : mm[1];
        bool d20 = (mm[2] == mm[0]);
        as[2] += d20 ? as[0] : 0.f;  bs[2] += d20 ? bs[0] : 0.f;
        mm[0]  = d20 ? DEAD : mm[0];
        bool d32 = (mm[3] == mm[2]);
        as[3] += d32 ? as[2] : 0.f;  bs[3] += d32 ? bs[2] : 0.f;
        mm[2]  = d32 ? DEAD : mm[2];
        bool d31 = (mm[3] == mm[1]);
        as[3] += d31 ? as[1] : 0.f;  bs[3] += d31 ? bs[1] : 0.f;
        mm[1]  = d31 ? DEAD : mm[1];
        bool d30 = (mm[3] == mm[0]);
        as[3] += d30 ? as[0] : 0.f;  bs[3] += d30 ? bs[0] : 0.f;
        mm[0]  = d30 ? DEAD : mm[0];
    }

    // Addresses now distinct (or scratch): batch loads -> adds -> stores.
    const int i0 = mm[0] * THREADS + tid;
    const int i1 = mm[1] * THREADS + tid;
    const int i2 = mm[2] * THREADS + tid;
    const int i3 = mm[3] * THREADS + tid;
    float2 v0 = slab[i0], v1 = slab[i1], v2 = slab[i2], v3 = slab[i3];
    v0.x += as[0]; v0.y += bs[0];
    v1.x += as[1]; v1.y += bs[1];
    v2.x += as[2]; v2.y += bs[2];
    v3.x += as[3]; v3.y += bs[3];
    slab[i0] = v0; slab[i1] = v1; slab[i2] = v2; slab[i3] = v3;

    return make_float4(os[0], os[1], os[2], os[3]);
}

__global__ __launch_bounds__(THREADS, 4)
void ssq_kernel(const float* __restrict__ x,
                const float* __restrict__ bins,
                float* __restrict__ out)
{
    __shared__ float  sbins[32];
    __shared__ float4 sTabP[NBUCKET];
    __shared__ float4 sTabQ[NBUCKET];
    __shared__ float  sEpsB;
    __shared__ float2 sSlab[ROWS * THREADS];
    __shared__ float  sQw[THREADS/32];
    __shared__ int    sLast;

    const int tid  = threadIdx.x;
    const int lane = tid & 31;
    const int warp = tid >> 5;

    const float C5  = 7.21347520444482f;
    const float C10 = 14.42695040888963f;

    // ---- Prologue (warp 0): sort bins, build prefix/suffix tables ----
    if (warp == 0) {
        float v = __ldg(&bins[lane]);
        #pragma unroll
        for (int kk = 2; kk <= 32; kk <<= 1) {
            #pragma unroll
            for (int j = kk >> 1; j > 0; j >>= 1) {
                float w = __shfl_xor_sync(FULL, v, j);
                bool takeMin = (((lane & j) == 0) == ((lane & kk) == 0));
                v = takeMin ? fminf(v, w) : fmaxf(v, w);
            }
        }
        sbins[lane] = v;               // ascending

        float sb = v;
        #pragma unroll
        for (int m = 16; m > 0; m >>= 1) sb += __shfl_xor_sync(FULL, sb, m);
        if (lane == 0) sEpsB = 1e-10f * sb;

        float e10 = ex2f_( C10 * v), f10 = ex2f_(-C10 * v);
        float e5  = ex2f_( C5  * v), f5  = ex2f_(-C5  * v);
        float eb  = e10 * v,         fb  = f10 * v;

        float p10 = e10, p5 = e5, pb = eb;          // inclusive prefix
        #pragma unroll
        for (int d = 1; d < 32; d <<= 1) {
            float t0 = __shfl_up_sync(FULL, p10, d);
            float t1 = __shfl_up_sync(FULL, p5,  d);
            float t2 = __shfl_up_sync(FULL, pb,  d);
            if (lane >= d) { p10 += t0; p5 += t1; pb += t2; }
        }
        float q10 = f10, q5 = f5, qb = fb;          // inclusive suffix
        #pragma unroll
        for (int d = 1; d < 32; d <<= 1) {
            float t0 = __shfl_down_sync(FULL, q10, d);
            float t1 = __shfl_down_sync(FULL, q5,  d);
            float t2 = __shfl_down_sync(FULL, qb,  d);
            if (lane + d < 32) { q10 += t0; q5 += t1; qb += t2; }
        }
        sTabP[lane + 1] = make_float4(p10, p5, pb, 0.f);
        sTabQ[lane]     = make_float4(q10, q5, qb, 0.f);
        if (lane == 0) {
            sTabP[0]  = make_float4(0.f, 0.f, 0.f, 0.f);
            sTabQ[32] = make_float4(0.f, 0.f, 0.f, 0.f);
        }
    }
    #pragma unroll
    for (int i = 0; i < ROWS; i++)
        sSlab[i * THREADS + tid] = make_float2(0.f, 0.f);
    __syncthreads();

    float rb[K];
    #pragma unroll
    for (int k = 0; k < K; k++) rb[k] = sbins[k];

    const float epsB = sEpsB;
    float qacc = 0.f;

    const int gtid = blockIdx.x * THREADS + tid;
    const int s = GRID * THREADS;
    const float4* x4 = (const float4*)x;
    float4* o4 = (float4*)out;
    const int n4 = NELEM / 4;
    const float4 z4 = make_float4(0.f, 0.f, 0.f, 0.f);

    // Double-buffered pair-of-float4 loop: loads issued one iteration ahead.
    int i = gtid;
    float4 c0 = (i < n4)     ? x4[i]     : z4;
    float4 c1 = (i + s < n4) ? x4[i + s] : z4;
    while (i < n4) {
        const int j = i + 2 * s;
        float4 nx0 = (j < n4)     ? x4[j]     : z4;
        float4 nx1 = (j + s < n4) ? x4[j + s] : z4;

        float4 r0 = do4(c0, sSlab, sTabP, sTabQ, rb, tid, epsB, qacc);
        o4[i] = r0;
        if (i + s < n4) {
            float4 r1 = do4(c1, sSlab, sTabP, sTabQ, rb, tid, epsB, qacc);
            o4[i + s] = r1;
        }
        c0 = nx0; c1 = nx1; i = j;
    }

    // ---- Block reduce ----
    #pragma unroll
    for (int m = 16; m > 0; m >>= 1) qacc += __shfl_xor_sync(FULL, qacc, m);
    if (lane == 0) sQw[warp] = qacc;
    __syncthreads();

    for (int m = warp; m < NBUCKET; m += THREADS/32) {
        float ta = 0.f, tb = 0.f;
        #pragma unroll
        for (int t = 0; t < THREADS; t += 32) {
            float2 v = sSlab[m * THREADS + t + lane];
            ta += v.x; tb += v.y;
        }
        #pragma unroll
        for (int d = 16; d > 0; d >>= 1) {
            ta += __shfl_xor_sync(FULL, ta, d);
            tb += __shfl_xor_sync(FULL, tb, d);
        }
        if (lane == 0) {
            atomicAdd(&g_A[m], ta);
            atomicAdd(&g_B[m], tb);
        }
    }
    if (tid == 0) {
        float q = 0.f;
        #pragma unroll
        for (int w = 0; w < THREADS/32; w++) q += sQw[w];
        atomicAdd(&g_Q, q);
    }

    // ---- Last-block finalize (self-cleaning) ----
    if (tid == 0) {
        __threadfence();
        unsigned int arrived = atomicAdd(&g_count, 1u);
        sLast = (arrived == GRID - 1u) ? 1 : 0;
    }
    __syncthreads();
    if (sLast) {
        __threadfence();
        if (tid < 32) {
            volatile float* va = g_A;
            volatile float* vb = g_B;
            float sa = va[lane + 1];                  // suffix over A (m>lane)
            #pragma unroll
            for (int d = 1; d < 32; d <<= 1) {
                float t = __shfl_down_sync(FULL, sa, d);
                if (lane + d < 32) sa += t;
            }
            float sbv = vb[lane];                     // prefix over B (m<=lane)
            #pragma unroll
            for (int d = 1; d < 32; d <<= 1) {
                float t = __shfl_up_sync(FULL, sbv, d);
                if (lane >= d) sbv += t;
            }
            float bk   = sbins[lane];
            float E10k = ex2f_( C10 * bk);
            float F10k = ex2f_(-C10 * bk);
            float u = E10k * sa + F10k * sbv;          // scaled by 2^-64
            float p = fmaf(u, 0x1p43f, 1e-10f);        // *2^64/NELEM + EPS
            float e = -p * logf(p);
            #pragma unroll
            for (int d = 16; d > 0; d >>= 1)
                e += __shfl_xor_sync(FULL, e, d);
            if (lane == 0) {
                volatile float* vq = &g_Q;
                out[NELEM]     = e;
                out[NELEM + 1] = 0.f;
                out[NELEM + 2] = vq[0] * (1.0f / (float)NELEM);
                out[NELEM + 3] = 0.f;
            }
        }
        __syncthreads();
        if (tid < NBUCKET) { g_A[tid] = 0.f; g_B[tid] = 0.f; }
        if (tid == 0) { g_Q = 0.f; g_count = 0u; }
    }
}

extern "C" void kernel_launch(void* const* d_in, const int* in_sizes, int n_in,
                              void* d_out, int out_size)
{
    const float* x    = (const float*)d_in[0];
    const float* bins = (const float*)d_in[1];
    if (n_in >= 2 && in_sizes[0] == K && in_sizes[1] != K) {
        const float* tmp = x; x = bins; bins = tmp;
    }
    float* out = (float*)d_out;

    ssq_kernel<<<GRID, THREADS>>>(x, bins, out);
}

// round 14
// speedup vs baseline: 1.3353x; 1.3353x over previous
#include <cuda_runtime.h>

#define K 32
#define NELEM (32*64*1024)
#define THREADS 128
#define GRID 592          // 148 x 4 CTAs = one wave
#define LUTN 1024
#define FULL 0xffffffffu

typedef unsigned long long u64;

// Global accumulators; last block self-cleans for graph replay.
__device__ float g_P[K];
__device__ float g_Q;
__device__ unsigned int g_count;

__device__ __forceinline__ float ex2f_(float x) {
    float r; asm("ex2.approx.ftz.f32 %0, %1;" : "=f"(r) : "f"(x)); return r;
}
__device__ __forceinline__ float rsqf_(float x) {
    float r; asm("rsqrt.approx.ftz.f32 %0, %1;" : "=f"(r) : "f"(x)); return r;
}
__device__ __forceinline__ u64 pack2(float lo, float hi) {
    u64 r; asm("mov.b64 %0, {%1, %2};" : "=l"(r) : "f"(lo), "f"(hi)); return r;
}
__device__ __forceinline__ float lo2(u64 v) {
    float lo, hi; asm("mov.b64 {%0, %1}, %2;" : "=f"(lo), "=f"(hi) : "l"(v)); return lo;
}
__device__ __forceinline__ float hi2(u64 v) {
    float lo, hi; asm("mov.b64 {%0, %1}, %2;" : "=f"(lo), "=f"(hi) : "l"(v)); return hi;
}
#define MUL2(o, a, b) asm("mul.rn.f32x2 %0, %1, %2;" : "=l"(o) : "l"(a), "l"(b))
#define ADD2(o, a, b) asm("add.rn.f32x2 %0, %1, %2;" : "=l"(o) : "l"(a), "l"(b))

__global__ __launch_bounds__(THREADS, 4)
void ssq_kernel(const float* __restrict__ x,
                const float* __restrict__ bins,
                float* __restrict__ out)
{
    __shared__ float sbins[K];
    __shared__ float sP10[K+1], sQ10[K+1], sP5[K+1], sQ5[K+1], sPB[K+1], sQB[K+1];
    __shared__ float sEpsB, sLo, sScale, sInvScale;
    __shared__ unsigned char sLUT[LUTN];
    __shared__ float sRed[THREADS/32][K];
    __shared__ float sQw[THREADS/32];
    __shared__ int   sLast;

    const int tid  = threadIdx.x;
    const int lane = tid & 31;
    const int warp = tid >> 5;

    const float C5  = 7.21347520444482f;    // 5*log2(e)
    const float C10 = 14.42695040888963f;   // 10*log2(e)

    // ---- Prologue (warp 0): sort bins, build prefix/suffix tables ----
    if (warp == 0) {
        float v = __ldg(&bins[lane]);
        #pragma unroll
        for (int kk = 2; kk <= 32; kk <<= 1) {
            #pragma unroll
            for (int j = kk >> 1; j > 0; j >>= 1) {
                float w = __shfl_xor_sync(FULL, v, j);
                bool takeMin = (((lane & j) == 0) == ((lane & kk) == 0));
                v = takeMin ? fminf(v, w) : fmaxf(v, w);
            }
        }
        sbins[lane] = v;               // ascending

        float bmin = __shfl_sync(FULL, v, 0);
        float bmax = __shfl_sync(FULL, v, 31);

        float sb = v;
        #pragma unroll
        for (int m = 16; m > 0; m >>= 1) sb += __shfl_xor_sync(FULL, sb, m);
        if (lane == 0) {
            sEpsB = 1e-10f * sb;
            sLo = bmin;
            float span = bmax - bmin + 1e-20f;
            sScale = (float)LUTN / span;
            sInvScale = span / (float)LUTN;
        }

        float e10 = ex2f_( C10 * v), f10 = ex2f_(-C10 * v);
        float e5  = ex2f_( C5  * v), f5  = ex2f_(-C5  * v);
        float eb  = e10 * v,         fb  = f10 * v;

        float p10 = e10, p5 = e5, pb = eb;          // inclusive prefix
        #pragma unroll
        for (int d = 1; d < 32; d <<= 1) {
            float t0 = __shfl_up_sync(FULL, p10, d);
            float t1 = __shfl_up_sync(FULL, p5,  d);
            float t2 = __shfl_up_sync(FULL, pb,  d);
            if (lane >= d) { p10 += t0; p5 += t1; pb += t2; }
        }
        float q10 = f10, q5 = f5, qb = fb;          // inclusive suffix
        #pragma unroll
        for (int d = 1; d < 32; d <<= 1) {
            float t0 = __shfl_down_sync(FULL, q10, d);
            float t1 = __shfl_down_sync(FULL, q5,  d);
            float t2 = __shfl_down_sync(FULL, qb,  d);
            if (lane + d < 32) { q10 += t0; q5 += t1; qb += t2; }
        }
        sP10[lane+1] = p10; sP5[lane+1] = p5; sPB[lane+1] = pb;
        sQ10[lane]   = q10; sQ5[lane]   = q5; sQB[lane]   = qb;
        if (lane == 0) {
            sP10[0] = 0.f; sP5[0] = 0.f; sPB[0] = 0.f;
            sQ10[K] = 0.f; sQ5[K] = 0.f; sQB[K] = 0.f;
        }
    }
    __syncthreads();

    // ---- LUT build (whole block): rank of each cell's left edge ----
    {
        const float blo = sLo, ivs = sInvScale;
        for (int c = tid; c < LUTN; c += THREADS) {
            float edge = fmaf((float)c, ivs, blo);
            int r = 0;
            #pragma unroll
            for (int k = 0; k < K; k++) r += (sbins[k] <= edge) ? 1 : 0;
            sLUT[c] = (unsigned char)r;
        }
    }

    // Per-thread packed constants: {exp(10 b_2j), exp(10 b_2j+1)} and negatives.
    u64 c10p[K/2], d10p[K/2];
    #pragma unroll
    for (int j = 0; j < K/2; j++) {
        float b0 = sbins[2*j], b1 = sbins[2*j+1];
        c10p[j] = pack2(ex2f_( C10 * b0), ex2f_( C10 * b1));
        d10p[j] = pack2(ex2f_(-C10 * b0), ex2f_(-C10 * b1));
    }
    __syncthreads();

    u64 sumP2[K/2];
    #pragma unroll
    for (int j = 0; j < K/2; j++) sumP2[j] = 0ull;
    float qacc = 0.f;

    const float epsB = sEpsB;
    const float blo  = sLo;
    const float scl  = sScale;

    const int gtid = blockIdx.x * THREADS + tid;
    const int s = GRID * THREADS;
    const float4* x4 = (const float4*)x;
    float4* o4 = (float4*)out;
    const int n4 = NELEM / 4;
    const float4 z4 = make_float4(0.f, 0.f, 0.f, 0.f);

    int i = gtid;
    float4 cur = (i < n4) ? x4[i] : z4;
    while (i < n4) {
        const int nj = i + s;
        float4 nxt = (nj < n4) ? x4[nj] : z4;

        float xs[4] = {cur.x, cur.y, cur.z, cur.w};
        float os[4];
        #pragma unroll
        for (int c = 0; c < 4; c++) {
            const float xe = xs[c];
            // rank via LUT + bounded exact refine (clamp in float first).
            float cf = fminf(fmaxf((xe - blo) * scl, 0.0f), (float)(LUTN - 1));
            int m = sLUT[(int)cf];
            #pragma unroll 1
            for (int r = 0; r < K; r++) { if (m < K && xe >= sbins[m]) m++; else break; }
            #pragma unroll 1
            for (int r = 0; r < K; r++) { if (m > 0 && xe < sbins[m-1]) m--; else break; }

            const float na = -C5 * xe;
            const float A  = ex2f_(na);        // exp(-5x)
            const float B  = ex2f_(-na);       // exp(+5x)
            const float A2 = A * A;
            const float B2 = B * B;

            const float S  = fmaf(A2, sP10[m], B2 * sQ10[m]);
            const float Hs = fmaf(A,  sP5[m],  B  * sQ5[m]);
            const float bR = fmaf(A2, sPB[m],  B2 * sQB[m]);
            const float rs = rsqf_(S);
            const float invS = rs * rs;
            qacc  = fmaf(Hs, rs, qacc);
            os[c] = fmaf(bR, invS, epsB);

            // sumP_k += soft_k = min(A2*invS*e10_k, B2*invS*f10_k), registers only.
            const float ai = A2 * invS;
            const float bi = B2 * invS;
            const u64 ais = pack2(ai, ai);
            const u64 bis = pack2(bi, bi);
            #pragma unroll
            for (int j = 0; j < K/2; j++) {
                u64 u, v;
                MUL2(u, ais, c10p[j]);
                MUL2(v, bis, d10p[j]);
                float e0 = fminf(lo2(u), lo2(v));   // FMNMX (alu pipe)
                float e1 = fminf(hi2(u), hi2(v));
                u64 e = pack2(e0, e1);
                ADD2(sumP2[j], sumP2[j], e);
            }
        }
        o4[i] = make_float4(os[0], os[1], os[2], os[3]);
        cur = nxt; i = nj;
    }

    // ---- Block reduce ----
    #pragma unroll
    for (int m = 16; m > 0; m >>= 1) {
        qacc += __shfl_xor_sync(FULL, qacc, m);
        #pragma unroll
        for (int j = 0; j < K/2; j++) {
            u64 o = __shfl_xor_sync(FULL, sumP2[j], m);
            ADD2(sumP2[j], sumP2[j], o);
        }
    }
    if (lane == 0) {
        #pragma unroll
        for (int j = 0; j < K/2; j++) {
            sRed[warp][2*j]   = lo2(sumP2[j]);
            sRed[warp][2*j+1] = hi2(sumP2[j]);
        }
        sQw[warp] = qacc;
    }
    __syncthreads();
    if (tid < K) {
        float t = 0.f;
        #pragma unroll
        for (int w = 0; w < THREADS/32; w++) t += sRed[w][tid];
        atomicAdd(&g_P[tid], t);
    }
    if (tid == 0) {
        float q = 0.f;
        #pragma unroll
        for (int w = 0; w < THREADS/32; w++) q += sQw[w];
        atomicAdd(&g_Q, q);
    }

    // ---- Last-block finalize (self-cleaning) ----
    if (tid == 0) {
        __threadfence();
        unsigned int arrived = atomicAdd(&g_count, 1u);
        sLast = (arrived == GRID - 1u) ? 1 : 0;
    }
    __syncthreads();
    if (sLast) {
        __threadfence();
        if (tid < 32) {
            const float invN = 1.0f / (float)NELEM;
            volatile float* gp = g_P;
            float p = fmaf(gp[lane], invN, 1e-10f);   // mean(soft_k) + EPS
            float e = -p * logf(p);
            #pragma unroll
            for (int d = 16; d > 0; d >>= 1)
                e += __shfl_xor_sync(FULL, e, d);
            if (lane == 0) {
                volatile float* vq = &g_Q;
                out[NELEM]     = e;                              // code entropy
                out[NELEM + 1] = 0.f;                            // TAU
                out[NELEM + 2] = vq[0] * (1.0f / (float)NELEM);  // quant loss
                out[NELEM + 3] = 0.f;                            // TAU2
            }
        }
        __syncthreads();
        if (tid < K) g_P[tid] = 0.f;
        if (tid == 0) { g_Q = 0.f; g_count = 0u; }
    }
}

extern "C" void kernel_launch(void* const* d_in, const int* in_sizes, int n_in,
                              void* d_out, int out_size)
{
    const float* x    = (const float*)d_in[0];
    const float* bins = (const float*)d_in[1];
    if (n_in >= 2 && in_sizes[0] == K && in_sizes[1] != K) {
        const float* tmp = x; x = bins; bins = tmp;
    }
    float* out = (float*)d_out;

    ssq_kernel<<<GRID, THREADS>>>(x, bins, out);
}